// round 15
// baseline (speedup 1.0000x reference)
#include <cuda_runtime.h>
#include <cuda_fp16.h>
#include <cstdint>
#include <math.h>

#define BB 4
#define SS 2048
#define DD 1024
#define BSR (BB * SS)
#define SCALE (1.0f / 32.0f)

// ---------------------------------------------------------------------------
// Scratch (__device__ globals). 1-term fp16 operands everywhere.
// ---------------------------------------------------------------------------
__device__ __align__(128) __half g_x_h[BSR * DD];
__device__ __align__(128) __half g_Wt_h[3 * DD * DD];
__device__ __align__(128) __half g_Q_h[BSR * DD];
__device__ __align__(128) __half g_K_h[BSR * DD];
__device__ __align__(128) __half g_V_h[BSR * DD];
__device__ __align__(128) __half g_Vt_h[(size_t)BB * DD * SS];
__device__ __align__(128) __half g_w_h[(size_t)BB * SS * SS];

// ---------------------------------------------------------------------------
// Helpers
// ---------------------------------------------------------------------------
__device__ __forceinline__ uint32_t smem_to_u32(const void* smem_ptr) {
    uint32_t addr;
    asm("{ .reg .u64 tmp; cvta.to.shared.u64 tmp, %1; cvt.u32.u64 %0, tmp; }"
        : "=r"(addr) : "l"(smem_ptr));
    return addr;
}

__device__ __forceinline__ void cga16(uint32_t dst, const void* src) {
    asm volatile("cp.async.cg.shared.global [%0], [%1], 16;" :: "r"(dst), "l"(src));
}
#define CP_COMMIT() asm volatile("cp.async.commit_group;" ::: "memory")
#define CP_WAIT3()  asm volatile("cp.async.wait_group 3;" ::: "memory")

#define LDSM4(r, a) \
    asm volatile("ldmatrix.sync.aligned.m8n8.x4.shared.b16 {%0,%1,%2,%3}, [%4];" \
        : "=r"((r)[0]), "=r"((r)[1]), "=r"((r)[2]), "=r"((r)[3]) : "r"(a))

__device__ __forceinline__ void mma16816h(float* d, const uint32_t* a,
                                          uint32_t b0, uint32_t b1) {
    asm volatile(
        "mma.sync.aligned.m16n8k16.row.col.f32.f16.f16.f32 "
        "{%0,%1,%2,%3}, {%4,%5,%6,%7}, {%8,%9}, {%0,%1,%2,%3};"
        : "+f"(d[0]), "+f"(d[1]), "+f"(d[2]), "+f"(d[3])
        : "r"(a[0]), "r"(a[1]), "r"(a[2]), "r"(a[3]), "r"(b0), "r"(b1));
}

__device__ __forceinline__ uint32_t packh(__half a, __half b) {
    __half2 t = __halves2half2(a, b);
    return *reinterpret_cast<uint32_t*>(&t);
}

// Packed 64B-row tile, XOR-16B swizzle (validated R6-R12)
__device__ __forceinline__ uint32_t sw64(int row, int cbyte) {
    return (uint32_t)(row * 64 + ((((cbyte >> 4) ^ ((row >> 1) & 3)) << 4) | (cbyte & 15)));
}

// ===========================================================================
// GEMM core: CTA tile 256(M) x 128(N), 256 threads = 8 warps (4M x 2N),
// warp 64x64. K-chunk 32. 1-term fp16. 5-stage cp.async, one sync/chunk.
// 1 CTA/SM, 16 warps/SM = 4 warps/SMSP (discriminating experiment vs R11's 2).
// Stage: A[16K] B[8K] = 24576 B; 5 stages = 122880 B.
// ===========================================================================
#define T_B   16384                      // B tile offset (A is 256 rows x 64B)
#define STAGE_B 24576
#define NSTAGE  5
#define SMEM_BYTES (NSTAGE * STAGE_B)    // 122880
#define NTHR  256

__device__ __forceinline__ void gemm_body(
    float acc[4][8][4],
    const __half* __restrict__ A, int lda,
    const __half* __restrict__ B, int ldb, int ktot)
{
    extern __shared__ char smem[];
    const uint32_t sb = smem_to_u32(smem);
    const int tid = threadIdx.x;
    const int w = tid >> 5, lane = tid & 31;
    const int wm = (w & 3) * 64, wn = (w >> 2) * 64;

    #pragma unroll
    for (int mi = 0; mi < 4; mi++)
        #pragma unroll
        for (int ni = 0; ni < 8; ni++)
            #pragma unroll
            for (int j = 0; j < 4; j++) acc[mi][ni][j] = 0.0f;

    // ldmatrix lane -> (row, 16B col) mapping (validated R4-R12)
    const int arow = lane & 15, acol = (lane >> 4) * 16;
    const int brow = (lane & 7) + ((lane >> 4) << 3);
    const int bcol = ((lane >> 3) & 1) * 16;

    // loader: 256 threads. A: 256 rows -> 4 rows/thread (r0+0,64,128,192).
    // B: 128 rows -> 2 rows/thread (r0+0,64). c0 = 16B column.
    const int r0 = tid >> 2, c0 = (tid & 3) * 16;
    uint32_t ofsA[4], ofsB[2];
    #pragma unroll
    for (int i = 0; i < 4; i++) ofsA[i] = sw64(r0 + i * 64, c0);
    #pragma unroll
    for (int i = 0; i < 2; i++) ofsB[i] = T_B + sw64(r0 + i * 64, c0);

    const int nch = ktot >> 5;

    auto load_stage = [&](int chunk, int buf) {
        const uint32_t base = sb + buf * STAGE_B;
        const int k0 = (chunk << 5) + (c0 >> 1);
        #pragma unroll
        for (int i = 0; i < 4; i++) {
            const size_t go = (size_t)(r0 + i * 64) * lda + k0;
            cga16(base + ofsA[i], A + go);
        }
        #pragma unroll
        for (int i = 0; i < 2; i++) {
            const size_t go = (size_t)(r0 + i * 64) * ldb + k0;
            cga16(base + ofsB[i], B + go);
        }
    };

    load_stage(0, 0); CP_COMMIT();
    load_stage(1, 1); CP_COMMIT();
    load_stage(2, 2); CP_COMMIT();
    load_stage(3, 3); CP_COMMIT();

    int buf = 0;
    for (int c = 0; c < nch; c++) {
        CP_WAIT3();            // oldest outstanding group (chunk c) done
        __syncthreads();       // also orders prior reads of the reused buffer
        if (c + 4 < nch) {
            int nb = buf + 4; if (nb >= NSTAGE) nb -= NSTAGE;
            load_stage(c + 4, nb);
        }
        CP_COMMIT();

        const uint32_t base = sb + buf * STAGE_B;
        if (++buf == NSTAGE) buf = 0;

        #pragma unroll
        for (int ks = 0; ks < 2; ks++) {
            const int kb = ks * 32;

            // B fragments: 4 n16 groups (warp's 64 columns)
            uint32_t Bf[4][4];
            #pragma unroll
            for (int nig = 0; nig < 4; nig++) {
                uint32_t ba = base + T_B + sw64(wn + nig * 16 + brow, kb + bcol);
                LDSM4(Bf[nig], ba);
            }

            #pragma unroll
            for (int mi = 0; mi < 4; mi++) {
                uint32_t aa = base + sw64(wm + mi * 16 + arow, kb + acol);
                uint32_t Af[4];
                LDSM4(Af, aa);
                #pragma unroll
                for (int nig = 0; nig < 4; nig++) {
                    mma16816h(acc[mi][2 * nig],     Af, Bf[nig][0], Bf[nig][1]);
                    mma16816h(acc[mi][2 * nig + 1], Af, Bf[nig][2], Bf[nig][3]);
                }
            }
        }
        // no trailing sync: next chunk's top sync orders reads before reuse
    }
}

// ---------------------------------------------------------------------------
// GEMM kernels (8 warps: wm=(w&3)*64, wn=(w>>2)*64; CTA tile 256x128)
// ---------------------------------------------------------------------------
__global__ void __launch_bounds__(NTHR, 1) qkv_gemm(
    const float* __restrict__ bq, const float* __restrict__ bk,
    const float* __restrict__ bv)
{
    const int z = blockIdx.z;
    const int m0 = blockIdx.y * 256;
    const int n0 = blockIdx.x * 128;
    const __half* Bp = g_Wt_h + (size_t)z * DD * DD + (size_t)n0 * DD;
    const float* bias; __half* Oh;
    if (z == 0)      { bias = bq; Oh = g_Q_h; }
    else if (z == 1) { bias = bk; Oh = g_K_h; }
    else             { bias = bv; Oh = g_V_h; }

    float acc[4][8][4];
    gemm_body(acc, g_x_h + (size_t)m0 * DD, DD, Bp, DD, DD);

    const int tid = threadIdx.x, w = tid >> 5, lane = tid & 31;
    const int wm = (w & 3) * 64, wn = (w >> 2) * 64;
    const int tg = lane >> 2, tig = lane & 3;
    #pragma unroll
    for (int mi = 0; mi < 4; mi++)
        #pragma unroll
        for (int ni = 0; ni < 8; ni++) {
            int row = m0 + wm + mi * 16 + tg;
            int col = n0 + wn + ni * 8 + tig * 2;
            float b0 = bias[col], b1 = bias[col + 1];
            #pragma unroll
            for (int h = 0; h < 2; h++) {
                float v0 = acc[mi][ni][2 * h]     + b0;
                float v1 = acc[mi][ni][2 * h + 1] + b1;
                size_t off = (size_t)(row + 8 * h) * DD + col;
                *(uint32_t*)(Oh + off) = packh(__float2half_rn(v0), __float2half_rn(v1));
            }
        }
}

__global__ void __launch_bounds__(NTHR, 1) scores_gemm(float* __restrict__ wgt)
{
    const int b = blockIdx.z;
    const int m0 = blockIdx.y * 256;
    const int n0 = blockIdx.x * 128;
    const size_t abase = ((size_t)b * SS + m0) * DD;
    const size_t bbase = ((size_t)b * SS + n0) * DD;

    float acc[4][8][4];
    gemm_body(acc, g_Q_h + abase, DD, g_K_h + bbase, DD, DD);

    float* C = wgt + (size_t)b * SS * SS;
    const int tid = threadIdx.x, w = tid >> 5, lane = tid & 31;
    const int wm = (w & 3) * 64, wn = (w >> 2) * 64;
    const int tg = lane >> 2, tig = lane & 3;
    #pragma unroll
    for (int mi = 0; mi < 4; mi++)
        #pragma unroll
        for (int ni = 0; ni < 8; ni++) {
            int row = m0 + wm + mi * 16 + tg;
            int col = n0 + wn + ni * 8 + tig * 2;
            #pragma unroll
            for (int h = 0; h < 2; h++) {
                float2 v;
                v.x = acc[mi][ni][2 * h]     * SCALE;
                v.y = acc[mi][ni][2 * h + 1] * SCALE;
                *(float2*)&C[(size_t)(row + 8 * h) * SS + col] = v;
            }
        }
}

__global__ void __launch_bounds__(NTHR, 1) att_gemm(float* __restrict__ att)
{
    const int b = blockIdx.z;
    const int m0 = blockIdx.y * 256;
    const int n0 = blockIdx.x * 128;
    const size_t abase = (size_t)b * SS * SS + (size_t)m0 * SS;
    const size_t bbase = ((size_t)b * DD + n0) * SS;

    float acc[4][8][4];
    gemm_body(acc, g_w_h + abase, SS, g_Vt_h + bbase, SS, SS);

    float* C = att + (size_t)b * SS * DD;
    const int tid = threadIdx.x, w = tid >> 5, lane = tid & 31;
    const int wm = (w & 3) * 64, wn = (w >> 2) * 64;
    const int tg = lane >> 2, tig = lane & 3;
    #pragma unroll
    for (int mi = 0; mi < 4; mi++)
        #pragma unroll
        for (int ni = 0; ni < 8; ni++) {
            int row = m0 + wm + mi * 16 + tg;
            int col = n0 + wn + ni * 8 + tig * 2;
            #pragma unroll
            for (int h = 0; h < 2; h++) {
                float2 v;
                v.x = acc[mi][ni][2 * h];
                v.y = acc[mi][ni][2 * h + 1];
                *(float2*)&C[(size_t)(row + 8 * h) * DD + col] = v;
            }
        }
}

// ---------------------------------------------------------------------------
// Conversion / transpose kernels
// ---------------------------------------------------------------------------
__global__ __launch_bounds__(256) void conv_x_kernel(const float* __restrict__ x)
{
    size_t i = (size_t)blockIdx.x * 256 + threadIdx.x;
    float4 v = ((const float4*)x)[i];
    uint2 uh;
    uh.x = packh(__float2half_rn(v.x), __float2half_rn(v.y));
    uh.y = packh(__float2half_rn(v.z), __float2half_rn(v.w));
    ((uint2*)g_x_h)[i] = uh;
}

__global__ __launch_bounds__(256) void wt_kernel(
    const float* __restrict__ Wq, const float* __restrict__ Wk,
    const float* __restrict__ Wv)
{
    const int z = blockIdx.z;
    const float* W = (z == 0) ? Wq : (z == 1) ? Wk : Wv;
    __half* Oh = g_Wt_h + (size_t)z * DD * DD;
    __shared__ float t[32][33];
    const int tx = threadIdx.x & 31, ty = threadIdx.x >> 5;
    const int x = blockIdx.x * 32 + tx;
    const int y0 = blockIdx.y * 32;
    #pragma unroll
    for (int i = 0; i < 4; i++)
        t[ty + i * 8][tx] = W[(size_t)(y0 + ty + i * 8) * DD + x];
    __syncthreads();
    const int xo = y0 + tx;
    const int yo0 = blockIdx.x * 32;
    #pragma unroll
    for (int i = 0; i < 4; i++) {
        size_t o = (size_t)(yo0 + ty + i * 8) * DD + xo;
        Oh[o] = __float2half_rn(t[tx][ty + i * 8]);
    }
}

__global__ __launch_bounds__(256) void vt_kernel()
{
    const int b = blockIdx.z;
    __shared__ __half th[32][33];
    const int tx = threadIdx.x & 31, ty = threadIdx.x >> 5;
    const int d0 = blockIdx.x * 32, s0 = blockIdx.y * 32;
    #pragma unroll
    for (int i = 0; i < 4; i++) {
        int s = s0 + ty + i * 8;
        th[ty + i * 8][tx] = g_V_h[(size_t)(b * SS + s) * DD + d0 + tx];
    }
    __syncthreads();
    #pragma unroll
    for (int i = 0; i < 4; i++) {
        int d = d0 + ty + i * 8, s = s0 + tx;
        g_Vt_h[((size_t)b * DD + d) * SS + s] = th[tx][ty + i * 8];
    }
}

// ---------------------------------------------------------------------------
// Reductions + softmax + layernorm
// ---------------------------------------------------------------------------
__device__ __forceinline__ float block_reduce_sum(float v, float* sred) {
    #pragma unroll
    for (int o = 16; o > 0; o >>= 1) v += __shfl_xor_sync(0xffffffffu, v, o);
    int wid = threadIdx.x >> 5, lane = threadIdx.x & 31;
    if (lane == 0) sred[wid] = v;
    __syncthreads();
    if (wid == 0) {
        float t = (lane < 8) ? sred[lane] : 0.0f;
        #pragma unroll
        for (int o = 4; o > 0; o >>= 1) t += __shfl_xor_sync(0xffffffffu, t, o);
        if (lane == 0) sred[0] = t;
    }
    __syncthreads();
    float r = sred[0];
    __syncthreads();
    return r;
}

__device__ __forceinline__ float block_reduce_max(float v, float* sred) {
    #pragma unroll
    for (int o = 16; o > 0; o >>= 1) v = fmaxf(v, __shfl_xor_sync(0xffffffffu, v, o));
    int wid = threadIdx.x >> 5, lane = threadIdx.x & 31;
    if (lane == 0) sred[wid] = v;
    __syncthreads();
    if (wid == 0) {
        float t = (lane < 8) ? sred[lane] : -1e30f;
        #pragma unroll
        for (int o = 4; o > 0; o >>= 1) t = fmaxf(t, __shfl_xor_sync(0xffffffffu, t, o));
        if (lane == 0) sred[0] = t;
    }
    __syncthreads();
    float r = sred[0];
    __syncthreads();
    return r;
}

__global__ __launch_bounds__(256) void softmax_kernel(float* __restrict__ w)
{
    const size_t base = (size_t)blockIdx.x * SS;
    float* p = w + base;
    const int tid = threadIdx.x;
    __shared__ float sred[8];

    float v[8];
    float m = -1e30f;
    #pragma unroll
    for (int i = 0; i < 8; i++) {
        v[i] = p[tid + i * 256];
        m = fmaxf(m, v[i]);
    }
    m = block_reduce_max(m, sred);

    float s = 0.0f;
    #pragma unroll
    for (int i = 0; i < 8; i++) {
        v[i] = __expf(v[i] - m);
        s += v[i];
    }
    s = block_reduce_sum(s, sred);
    float inv = 1.0f / s;
    #pragma unroll
    for (int i = 0; i < 8; i++) {
        int idx = tid + i * 256;
        float wv = v[i] * inv;
        p[idx] = wv;
        g_w_h[base + idx] = __float2half_rn(wv);
    }
}

__global__ __launch_bounds__(256) void ln_kernel(
    const float* __restrict__ x, const float* __restrict__ gamma,
    const float* __restrict__ beta, const float* __restrict__ att,
    float* __restrict__ out1)
{
    const size_t row = blockIdx.x;
    const float* xr = x   + row * DD;
    const float* ar = att + row * DD;
    float* orow = out1 + row * DD;
    const int tid = threadIdx.x;
    __shared__ float sred[8];

    float v[4];
    float s = 0.0f;
    #pragma unroll
    for (int i = 0; i < 4; i++) {
        int c = tid + i * 256;
        v[i] = xr[c] + ar[c];
        s += v[i];
    }
    s = block_reduce_sum(s, sred);
    float mu = s * (1.0f / DD);

    float s2 = 0.0f;
    #pragma unroll
    for (int i = 0; i < 4; i++) {
        float d = v[i] - mu;
        s2 += d * d;
    }
    s2 = block_reduce_sum(s2, sred);
    float rstd = rsqrtf(s2 * (1.0f / DD) + 1e-5f);

    #pragma unroll
    for (int i = 0; i < 4; i++) {
        int c = tid + i * 256;
        orow[c] = (v[i] - mu) * rstd * gamma[c] + beta[c];
    }
}

// ---------------------------------------------------------------------------
// Launch. scores_gemm stays the 4th launch for ncu visibility.
// ---------------------------------------------------------------------------
extern "C" void kernel_launch(void* const* d_in, const int* in_sizes, int n_in,
                              void* d_out, int out_size)
{
    const float* x     = (const float*)d_in[0];
    const float* Wk    = (const float*)d_in[1];
    const float* bk    = (const float*)d_in[2];
    const float* Wq    = (const float*)d_in[3];
    const float* bq    = (const float*)d_in[4];
    const float* Wv    = (const float*)d_in[5];
    const float* bv    = (const float*)d_in[6];
    const float* gamma = (const float*)d_in[7];
    const float* beta  = (const float*)d_in[8];

    float* out  = (float*)d_out;
    float* out1 = out;                          // [B,S,D]
    float* att  = out + (size_t)BSR * DD;       // [B,S,D]
    float* wgt  = out + (size_t)2 * BSR * DD;   // [B,S,S]

    cudaFuncSetAttribute(qkv_gemm,    cudaFuncAttributeMaxDynamicSharedMemorySize, SMEM_BYTES);
    cudaFuncSetAttribute(scores_gemm, cudaFuncAttributeMaxDynamicSharedMemorySize, SMEM_BYTES);
    cudaFuncSetAttribute(att_gemm,    cudaFuncAttributeMaxDynamicSharedMemorySize, SMEM_BYTES);

    // 1) fp32 -> fp16 conversions
    conv_x_kernel<<<BSR * DD / 4 / 256, 256>>>(x);
    wt_kernel<<<dim3(32, 32, 3), 256>>>(Wq, Wk, Wv);
    // 2) QKV projections
    qkv_gemm<<<dim3(DD / 128, BSR / 256, 3), NTHR, SMEM_BYTES>>>(bq, bk, bv);
    // 3) scores = Q K^T * scale   (4th launch -> profiled by ncu)
    scores_gemm<<<dim3(SS / 128, SS / 256, BB), NTHR, SMEM_BYTES>>>(wgt);
    // 4) V transpose
    vt_kernel<<<dim3(DD / 32, SS / 32, BB), 256>>>();
    // 5) softmax
    softmax_kernel<<<BSR, 256>>>(wgt);
    // 6) att = weight @ V
    att_gemm<<<dim3(DD / 128, SS / 256, BB), NTHR, SMEM_BYTES>>>(att);
    // 7) residual + LayerNorm
    ln_kernel<<<BSR, 256>>>(x, gamma, beta, att, out1);
}

// round 17
// speedup vs baseline: 1.3045x; 1.3045x over previous
#include <cuda_runtime.h>
#include <cuda_fp16.h>
#include <cstdint>
#include <math.h>

#define BB 4
#define SS 2048
#define DD 1024
#define BSR (BB * SS)
#define SCALE (1.0f / 32.0f)

// ---------------------------------------------------------------------------
// Scratch (__device__ globals). 1-term fp16 operands everywhere.
// ---------------------------------------------------------------------------
__device__ __align__(128) __half g_x_h[BSR * DD];
__device__ __align__(128) __half g_Wt_h[3 * DD * DD];
__device__ __align__(128) __half g_Q_h[BSR * DD];
__device__ __align__(128) __half g_K_h[BSR * DD];
__device__ __align__(128) __half g_V_h[BSR * DD];
__device__ __align__(128) __half g_Vt_h[(size_t)BB * DD * SS];
__device__ __align__(128) __half g_w_h[(size_t)BB * SS * SS];

// ---------------------------------------------------------------------------
// Helpers
// ---------------------------------------------------------------------------
__device__ __forceinline__ uint32_t smem_to_u32(const void* smem_ptr) {
    uint32_t addr;
    asm("{ .reg .u64 tmp; cvta.to.shared.u64 tmp, %1; cvt.u32.u64 %0, tmp; }"
        : "=r"(addr) : "l"(smem_ptr));
    return addr;
}

__device__ __forceinline__ void cga16(uint32_t dst, const void* src) {
    asm volatile("cp.async.cg.shared.global [%0], [%1], 16;" :: "r"(dst), "l"(src));
}
#define CP_COMMIT() asm volatile("cp.async.commit_group;" ::: "memory")
#define CP_WAIT3()  asm volatile("cp.async.wait_group 3;" ::: "memory")

#define LDSM4(r, a) \
    asm volatile("ldmatrix.sync.aligned.m8n8.x4.shared.b16 {%0,%1,%2,%3}, [%4];" \
        : "=r"((r)[0]), "=r"((r)[1]), "=r"((r)[2]), "=r"((r)[3]) : "r"(a))

__device__ __forceinline__ void mma16816h(float* d, const uint32_t* a,
                                          uint32_t b0, uint32_t b1) {
    asm volatile(
        "mma.sync.aligned.m16n8k16.row.col.f32.f16.f16.f32 "
        "{%0,%1,%2,%3}, {%4,%5,%6,%7}, {%8,%9}, {%0,%1,%2,%3};"
        : "+f"(d[0]), "+f"(d[1]), "+f"(d[2]), "+f"(d[3])
        : "r"(a[0]), "r"(a[1]), "r"(a[2]), "r"(a[3]), "r"(b0), "r"(b1));
}

__device__ __forceinline__ uint32_t packh(__half a, __half b) {
    __half2 t = __halves2half2(a, b);
    return *reinterpret_cast<uint32_t*>(&t);
}

// Packed 64B-row tile, XOR-16B swizzle (validated R6-R15)
__device__ __forceinline__ uint32_t sw64(int row, int cbyte) {
    return (uint32_t)(row * 64 + ((((cbyte >> 4) ^ ((row >> 1) & 3)) << 4) | (cbyte & 15)));
}

// ===========================================================================
// GEMM core (best measured config, R11): CTA tile 128x128, 128 threads =
// 4 warps (2M x 2N), warp 64x64. K-chunk 32. 1-term fp16. 5-stage cp.async,
// one sync per chunk, 2 CTAs/SM.
// Stage: A[8K] B[8K] = 16384 B; 5 stages = 81920 B.
// ===========================================================================
#define T_B   8192
#define STAGE_B 16384
#define NSTAGE  5
#define SMEM_BYTES (NSTAGE * STAGE_B)   // 81920
#define NTHR  128

__device__ __forceinline__ void gemm_body(
    float acc[4][8][4],
    const __half* __restrict__ A, int lda,
    const __half* __restrict__ B, int ldb, int ktot)
{
    extern __shared__ char smem[];
    const uint32_t sb = smem_to_u32(smem);
    const int tid = threadIdx.x;
    const int w = tid >> 5, lane = tid & 31;
    const int wm = (w & 1) * 64, wn = (w >> 1) * 64;

    #pragma unroll
    for (int mi = 0; mi < 4; mi++)
        #pragma unroll
        for (int ni = 0; ni < 8; ni++)
            #pragma unroll
            for (int j = 0; j < 4; j++) acc[mi][ni][j] = 0.0f;

    // ldmatrix lane -> (row, 16B col) mapping (validated R4-R15)
    const int arow = lane & 15, acol = (lane >> 4) * 16;
    const int brow = (lane & 7) + ((lane >> 4) << 3);
    const int bcol = ((lane >> 3) & 1) * 16;

    // loader: 128 threads, 4 rows per thread per tile (r, r+32, r+64, r+96)
    const int r0 = tid >> 2, c0 = (tid & 3) * 16;
    uint32_t ofs[4];
    #pragma unroll
    for (int i = 0; i < 4; i++) ofs[i] = sw64(r0 + i * 32, c0);

    const int nch = ktot >> 5;

    auto load_stage = [&](int chunk, int buf) {
        const uint32_t base = sb + buf * STAGE_B;
        const int k0 = (chunk << 5) + (c0 >> 1);
        #pragma unroll
        for (int i = 0; i < 4; i++) {
            const size_t go = (size_t)(r0 + i * 32) * lda + k0;
            cga16(base + ofs[i], A + go);
        }
        #pragma unroll
        for (int i = 0; i < 4; i++) {
            const size_t go = (size_t)(r0 + i * 32) * ldb + k0;
            cga16(base + T_B + ofs[i], B + go);
        }
    };

    load_stage(0, 0); CP_COMMIT();
    load_stage(1, 1); CP_COMMIT();
    load_stage(2, 2); CP_COMMIT();
    load_stage(3, 3); CP_COMMIT();

    int buf = 0;
    for (int c = 0; c < nch; c++) {
        CP_WAIT3();            // oldest outstanding group (chunk c) done
        __syncthreads();       // also orders prior reads of the reused buffer
        if (c + 4 < nch) {
            int nb = buf + 4; if (nb >= NSTAGE) nb -= NSTAGE;
            load_stage(c + 4, nb);
        }
        CP_COMMIT();

        const uint32_t base = sb + buf * STAGE_B;
        if (++buf == NSTAGE) buf = 0;

        #pragma unroll
        for (int ks = 0; ks < 2; ks++) {
            const int kb = ks * 32;

            // B fragments: 4 n16 groups (64 columns)
            uint32_t Bf[4][4];
            #pragma unroll
            for (int nig = 0; nig < 4; nig++) {
                uint32_t ba = base + T_B + sw64(wn + nig * 16 + brow, kb + bcol);
                LDSM4(Bf[nig], ba);
            }

            #pragma unroll
            for (int mi = 0; mi < 4; mi++) {
                uint32_t aa = base + sw64(wm + mi * 16 + arow, kb + acol);
                uint32_t Af[4];
                LDSM4(Af, aa);
                #pragma unroll
                for (int nig = 0; nig < 4; nig++) {
                    mma16816h(acc[mi][2 * nig],     Af, Bf[nig][0], Bf[nig][1]);
                    mma16816h(acc[mi][2 * nig + 1], Af, Bf[nig][2], Bf[nig][3]);
                }
            }
        }
        // no trailing sync: next chunk's top sync orders reads before reuse
    }
}

// ---------------------------------------------------------------------------
// GEMM kernels (4 warps: wm=(w&1)*64, wn=(w>>1)*64)
// ---------------------------------------------------------------------------
__global__ void __launch_bounds__(NTHR, 2) qkv_gemm(
    const float* __restrict__ bq, const float* __restrict__ bk,
    const float* __restrict__ bv)
{
    const int z = blockIdx.z;
    const int m0 = blockIdx.y * 128;
    const int n0 = blockIdx.x * 128;
    const __half* Bp = g_Wt_h + (size_t)z * DD * DD + (size_t)n0 * DD;
    const float* bias; __half* Oh;
    if (z == 0)      { bias = bq; Oh = g_Q_h; }
    else if (z == 1) { bias = bk; Oh = g_K_h; }
    else             { bias = bv; Oh = g_V_h; }

    float acc[4][8][4];
    gemm_body(acc, g_x_h + (size_t)m0 * DD, DD, Bp, DD, DD);

    const int tid = threadIdx.x, w = tid >> 5, lane = tid & 31;
    const int wm = (w & 1) * 64, wn = (w >> 1) * 64;
    const int tg = lane >> 2, tig = lane & 3;
    #pragma unroll
    for (int mi = 0; mi < 4; mi++)
        #pragma unroll
        for (int ni = 0; ni < 8; ni++) {
            int row = m0 + wm + mi * 16 + tg;
            int col = n0 + wn + ni * 8 + tig * 2;
            float b0 = bias[col], b1 = bias[col + 1];
            #pragma unroll
            for (int h = 0; h < 2; h++) {
                float v0 = acc[mi][ni][2 * h]     + b0;
                float v1 = acc[mi][ni][2 * h + 1] + b1;
                size_t off = (size_t)(row + 8 * h) * DD + col;
                *(uint32_t*)(Oh + off) = packh(__float2half_rn(v0), __float2half_rn(v1));
            }
        }
}

__global__ void __launch_bounds__(NTHR, 2) scores_gemm(float* __restrict__ wgt)
{
    const int b = blockIdx.z;
    const int m0 = blockIdx.y * 128;
    const int n0 = blockIdx.x * 128;
    const size_t abase = ((size_t)b * SS + m0) * DD;
    const size_t bbase = ((size_t)b * SS + n0) * DD;

    float acc[4][8][4];
    gemm_body(acc, g_Q_h + abase, DD, g_K_h + bbase, DD, DD);

    float* C = wgt + (size_t)b * SS * SS;
    const int tid = threadIdx.x, w = tid >> 5, lane = tid & 31;
    const int wm = (w & 1) * 64, wn = (w >> 1) * 64;
    const int tg = lane >> 2, tig = lane & 3;
    #pragma unroll
    for (int mi = 0; mi < 4; mi++)
        #pragma unroll
        for (int ni = 0; ni < 8; ni++) {
            int row = m0 + wm + mi * 16 + tg;
            int col = n0 + wn + ni * 8 + tig * 2;
            #pragma unroll
            for (int h = 0; h < 2; h++) {
                float2 v;
                v.x = acc[mi][ni][2 * h]     * SCALE;
                v.y = acc[mi][ni][2 * h + 1] * SCALE;
                *(float2*)&C[(size_t)(row + 8 * h) * SS + col] = v;
            }
        }
}

__global__ void __launch_bounds__(NTHR, 2) att_gemm(float* __restrict__ att)
{
    const int b = blockIdx.z;
    const int m0 = blockIdx.y * 128;
    const int n0 = blockIdx.x * 128;
    const size_t abase = (size_t)b * SS * SS + (size_t)m0 * SS;
    const size_t bbase = ((size_t)b * DD + n0) * SS;

    float acc[4][8][4];
    gemm_body(acc, g_w_h + abase, SS, g_Vt_h + bbase, SS, SS);

    float* C = att + (size_t)b * SS * DD;
    const int tid = threadIdx.x, w = tid >> 5, lane = tid & 31;
    const int wm = (w & 1) * 64, wn = (w >> 1) * 64;
    const int tg = lane >> 2, tig = lane & 3;
    #pragma unroll
    for (int mi = 0; mi < 4; mi++)
        #pragma unroll
        for (int ni = 0; ni < 8; ni++) {
            int row = m0 + wm + mi * 16 + tg;
            int col = n0 + wn + ni * 8 + tig * 2;
            #pragma unroll
            for (int h = 0; h < 2; h++) {
                float2 v;
                v.x = acc[mi][ni][2 * h];
                v.y = acc[mi][ni][2 * h + 1];
                *(float2*)&C[(size_t)(row + 8 * h) * DD + col] = v;
            }
        }
}

// ---------------------------------------------------------------------------
// Conversion / transpose kernels
// ---------------------------------------------------------------------------
__global__ __launch_bounds__(256) void conv_x_kernel(const float* __restrict__ x)
{
    size_t i = (size_t)blockIdx.x * 256 + threadIdx.x;
    float4 v = ((const float4*)x)[i];
    uint2 uh;
    uh.x = packh(__float2half_rn(v.x), __float2half_rn(v.y));
    uh.y = packh(__float2half_rn(v.z), __float2half_rn(v.w));
    ((uint2*)g_x_h)[i] = uh;
}

__global__ __launch_bounds__(256) void wt_kernel(
    const float* __restrict__ Wq, const float* __restrict__ Wk,
    const float* __restrict__ Wv)
{
    const int z = blockIdx.z;
    const float* W = (z == 0) ? Wq : (z == 1) ? Wk : Wv;
    __half* Oh = g_Wt_h + (size_t)z * DD * DD;
    __shared__ float t[32][33];
    const int tx = threadIdx.x & 31, ty = threadIdx.x >> 5;
    const int x = blockIdx.x * 32 + tx;
    const int y0 = blockIdx.y * 32;
    #pragma unroll
    for (int i = 0; i < 4; i++)
        t[ty + i * 8][tx] = W[(size_t)(y0 + ty + i * 8) * DD + x];
    __syncthreads();
    const int xo = y0 + tx;
    const int yo0 = blockIdx.x * 32;
    #pragma unroll
    for (int i = 0; i < 4; i++) {
        size_t o = (size_t)(yo0 + ty + i * 8) * DD + xo;
        Oh[o] = __float2half_rn(t[tx][ty + i * 8]);
    }
}

__global__ __launch_bounds__(256) void vt_kernel()
{
    const int b = blockIdx.z;
    __shared__ __half th[32][33];
    const int tx = threadIdx.x & 31, ty = threadIdx.x >> 5;
    const int d0 = blockIdx.x * 32, s0 = blockIdx.y * 32;
    #pragma unroll
    for (int i = 0; i < 4; i++) {
        int s = s0 + ty + i * 8;
        th[ty + i * 8][tx] = g_V_h[(size_t)(b * SS + s) * DD + d0 + tx];
    }
    __syncthreads();
    #pragma unroll
    for (int i = 0; i < 4; i++) {
        int d = d0 + ty + i * 8, s = s0 + tx;
        g_Vt_h[((size_t)b * DD + d) * SS + s] = th[tx][ty + i * 8];
    }
}

// ---------------------------------------------------------------------------
// Reductions + softmax + layernorm
// ---------------------------------------------------------------------------
__device__ __forceinline__ float block_reduce_sum(float v, float* sred) {
    #pragma unroll
    for (int o = 16; o > 0; o >>= 1) v += __shfl_xor_sync(0xffffffffu, v, o);
    int wid = threadIdx.x >> 5, lane = threadIdx.x & 31;
    if (lane == 0) sred[wid] = v;
    __syncthreads();
    if (wid == 0) {
        float t = (lane < 8) ? sred[lane] : 0.0f;
        #pragma unroll
        for (int o = 4; o > 0; o >>= 1) t += __shfl_xor_sync(0xffffffffu, t, o);
        if (lane == 0) sred[0] = t;
    }
    __syncthreads();
    float r = sred[0];
    __syncthreads();
    return r;
}

__device__ __forceinline__ float block_reduce_max(float v, float* sred) {
    #pragma unroll
    for (int o = 16; o > 0; o >>= 1) v = fmaxf(v, __shfl_xor_sync(0xffffffffu, v, o));
    int wid = threadIdx.x >> 5, lane = threadIdx.x & 31;
    if (lane == 0) sred[wid] = v;
    __syncthreads();
    if (wid == 0) {
        float t = (lane < 8) ? sred[lane] : -1e30f;
        #pragma unroll
        for (int o = 4; o > 0; o >>= 1) t = fmaxf(t, __shfl_xor_sync(0xffffffffu, t, o));
        if (lane == 0) sred[0] = t;
    }
    __syncthreads();
    float r = sred[0];
    __syncthreads();
    return r;
}

__global__ __launch_bounds__(256) void softmax_kernel(float* __restrict__ w)
{
    const size_t base = (size_t)blockIdx.x * SS;
    float* p = w + base;
    const int tid = threadIdx.x;
    __shared__ float sred[8];

    float v[8];
    float m = -1e30f;
    #pragma unroll
    for (int i = 0; i < 8; i++) {
        v[i] = p[tid + i * 256];
        m = fmaxf(m, v[i]);
    }
    m = block_reduce_max(m, sred);

    float s = 0.0f;
    #pragma unroll
    for (int i = 0; i < 8; i++) {
        v[i] = __expf(v[i] - m);
        s += v[i];
    }
    s = block_reduce_sum(s, sred);
    float inv = 1.0f / s;
    #pragma unroll
    for (int i = 0; i < 8; i++) {
        int idx = tid + i * 256;
        float wv = v[i] * inv;
        p[idx] = wv;
        g_w_h[base + idx] = __float2half_rn(wv);
    }
}

__global__ __launch_bounds__(256) void ln_kernel(
    const float* __restrict__ x, const float* __restrict__ gamma,
    const float* __restrict__ beta, const float* __restrict__ att,
    float* __restrict__ out1)
{
    const size_t row = blockIdx.x;
    const float* xr = x   + row * DD;
    const float* ar = att + row * DD;
    float* orow = out1 + row * DD;
    const int tid = threadIdx.x;
    __shared__ float sred[8];

    float v[4];
    float s = 0.0f;
    #pragma unroll
    for (int i = 0; i < 4; i++) {
        int c = tid + i * 256;
        v[i] = xr[c] + ar[c];
        s += v[i];
    }
    s = block_reduce_sum(s, sred);
    float mu = s * (1.0f / DD);

    float s2 = 0.0f;
    #pragma unroll
    for (int i = 0; i < 4; i++) {
        float d = v[i] - mu;
        s2 += d * d;
    }
    s2 = block_reduce_sum(s2, sred);
    float rstd = rsqrtf(s2 * (1.0f / DD) + 1e-5f);

    #pragma unroll
    for (int i = 0; i < 4; i++) {
        int c = tid + i * 256;
        orow[c] = (v[i] - mu) * rstd * gamma[c] + beta[c];
    }
}

// ---------------------------------------------------------------------------
// Launch. scores_gemm stays the 4th launch for ncu visibility.
// ---------------------------------------------------------------------------
extern "C" void kernel_launch(void* const* d_in, const int* in_sizes, int n_in,
                              void* d_out, int out_size)
{
    const float* x     = (const float*)d_in[0];
    const float* Wk    = (const float*)d_in[1];
    const float* bk    = (const float*)d_in[2];
    const float* Wq    = (const float*)d_in[3];
    const float* bq    = (const float*)d_in[4];
    const float* Wv    = (const float*)d_in[5];
    const float* bv    = (const float*)d_in[6];
    const float* gamma = (const float*)d_in[7];
    const float* beta  = (const float*)d_in[8];

    float* out  = (float*)d_out;
    float* out1 = out;                          // [B,S,D]
    float* att  = out + (size_t)BSR * DD;       // [B,S,D]
    float* wgt  = out + (size_t)2 * BSR * DD;   // [B,S,S]

    cudaFuncSetAttribute(qkv_gemm,    cudaFuncAttributeMaxDynamicSharedMemorySize, SMEM_BYTES);
    cudaFuncSetAttribute(scores_gemm, cudaFuncAttributeMaxDynamicSharedMemorySize, SMEM_BYTES);
    cudaFuncSetAttribute(att_gemm,    cudaFuncAttributeMaxDynamicSharedMemorySize, SMEM_BYTES);

    // 1) fp32 -> fp16 conversions
    conv_x_kernel<<<BSR * DD / 4 / 256, 256>>>(x);
    wt_kernel<<<dim3(32, 32, 3), 256>>>(Wq, Wk, Wv);
    // 2) QKV projections
    qkv_gemm<<<dim3(DD / 128, BSR / 128, 3), NTHR, SMEM_BYTES>>>(bq, bk, bv);
    // 3) scores = Q K^T * scale   (4th launch -> profiled by ncu)
    scores_gemm<<<dim3(SS / 128, SS / 128, BB), NTHR, SMEM_BYTES>>>(wgt);
    // 4) V transpose
    vt_kernel<<<dim3(DD / 32, SS / 32, BB), 256>>>();
    // 5) softmax
    softmax_kernel<<<BSR, 256>>>(wgt);
    // 6) att = weight @ V
    att_gemm<<<dim3(DD / 128, SS / 128, BB), NTHR, SMEM_BYTES>>>(att);
    // 7) residual + LayerNorm
    ln_kernel<<<BSR, 256>>>(x, gamma, beta, att, out1);
}